// round 3
// baseline (speedup 1.0000x reference)
#include <cuda_runtime.h>
#include <math.h>

// ---------------------------------------------------------------------------
// HyperbolicFullAttention: B=4, N=2048, D_IN=128 (in=129), H=8, D_OUT=64 (amb=65)
//
// Key identity: softmax scores = (2 + 2*li)/(scale+eps) + bias where
// li = -q0*k0 + qs.ks. Constants cancel in softmax; alpha = 2/(scale+eps)
// folds into Q. Store Q~ = (-alpha*q0, alpha*qs) -> scores = dot65(Q~, K).
// ---------------------------------------------------------------------------

#define B_    4
#define N_    2048
#define DIN_  129        // D_IN + 1
#define H_    8
#define AMB_  65         // D_OUT + 1
#define PAD_  68         // padded ambient (float4-friendly)
#define NT_   (N_ / 64)  // 32 tiles of 64
#define EPSF  1e-7f
#define XST_  8388       // float offset of Ws in proj smem (129*65=8385 rounded to mult of 4)

// Scratch (static device arrays; allocation is forbidden). 16B-aligned for float4.
__device__ __align__(16) float g_Q[(size_t)B_ * H_ * PAD_ * N_];   // (B,H,68,N) d-major, alpha-folded, d0 negated
__device__ __align__(16) float g_K[(size_t)B_ * H_ * PAD_ * N_];   // (B,H,68,N) d-major
__device__ __align__(16) float g_V[(size_t)B_ * H_ * N_ * PAD_];   // (B,H,N,68) row-major
__device__ __align__(16) float g_Mid[(size_t)B_ * N_ * H_ * PAD_]; // (B,N,H,68) per-head normalized midpoints

// ---------------------------------------------------------------------------
// Kernel 1: projection + lift.  grid (N/64, H, B*3) ; z: b = z/3, m = z%3
// ---------------------------------------------------------------------------
__global__ __launch_bounds__(256) void proj_kernel(
    const float* __restrict__ x,
    const float* __restrict__ Wq, const float* __restrict__ Wk, const float* __restrict__ Wv,
    const float* __restrict__ bq, const float* __restrict__ bk, const float* __restrict__ bv,
    const float* __restrict__ scale)
{
    extern __shared__ float sm[];
    float* xsT = sm;            // [129][65]  (x tile, transposed, stride 65: conflict-free)
    float* Ws  = sm + XST_;     // [129][68]  (offset mult of 4 floats -> float4-aligned)

    const int tid = threadIdx.x;
    const int tx = tid & 15, ty = tid >> 4;
    const int n0 = blockIdx.x * 64;
    const int h  = blockIdx.y;
    const int b  = blockIdx.z / 3;
    const int m  = blockIdx.z % 3;

    const float* W    = (m == 0) ? Wq : (m == 1) ? Wk : Wv;
    const float* bias = (m == 0) ? bq : (m == 1) ? bk : bv;

    // load x tile (coalesced read, stride-65 shared write = conflict-free)
    const float* xbase = x + ((size_t)b * N_ + n0) * DIN_;
    for (int idx = tid; idx < 64 * DIN_; idx += 256) {
        int r = idx / DIN_;
        int i = idx - r * DIN_;
        xsT[i * 65 + r] = xbase[idx];
    }
    // load W[h] (129 x 64), stride-68 shared
    const float* Wh = W + (size_t)h * DIN_ * 64;
    for (int idx = tid; idx < DIN_ * 64; idx += 256) {
        int i = idx >> 6, d = idx & 63;
        Ws[i * PAD_ + d] = Wh[idx];
    }
    __syncthreads();

    const int r0 = ty * 4, c0 = tx * 4;
    float acc[4][4] = {};
    for (int i = 0; i < DIN_; ++i) {
        const float* xr = &xsT[i * 65 + r0];
        float a0 = xr[0], a1 = xr[1], a2 = xr[2], a3 = xr[3];
        float4 w4 = *(const float4*)&Ws[i * PAD_ + c0];
        acc[0][0] = fmaf(a0, w4.x, acc[0][0]); acc[0][1] = fmaf(a0, w4.y, acc[0][1]);
        acc[0][2] = fmaf(a0, w4.z, acc[0][2]); acc[0][3] = fmaf(a0, w4.w, acc[0][3]);
        acc[1][0] = fmaf(a1, w4.x, acc[1][0]); acc[1][1] = fmaf(a1, w4.y, acc[1][1]);
        acc[1][2] = fmaf(a1, w4.z, acc[1][2]); acc[1][3] = fmaf(a1, w4.w, acc[1][3]);
        acc[2][0] = fmaf(a2, w4.x, acc[2][0]); acc[2][1] = fmaf(a2, w4.y, acc[2][1]);
        acc[2][2] = fmaf(a2, w4.z, acc[2][2]); acc[2][3] = fmaf(a2, w4.w, acc[2][3]);
        acc[3][0] = fmaf(a3, w4.x, acc[3][0]); acc[3][1] = fmaf(a3, w4.y, acc[3][1]);
        acc[3][2] = fmaf(a3, w4.z, acc[3][2]); acc[3][3] = fmaf(a3, w4.w, acc[3][3]);
    }
    // bias (scalar loads: avoid any alignment assumption on harness buffers)
    const float* bh = &bias[h * 64 + c0];
    float b0 = bh[0], b1 = bh[1], b2 = bh[2], b3 = bh[3];
    #pragma unroll
    for (int r = 0; r < 4; ++r) {
        acc[r][0] += b0; acc[r][1] += b1; acc[r][2] += b2; acc[r][3] += b3;
    }
    // row sum of squares over all 64 spatial dims (16 tx lanes hold 4 dims each)
    float ss[4];
    #pragma unroll
    for (int r = 0; r < 4; ++r) {
        float v = acc[r][0]*acc[r][0] + acc[r][1]*acc[r][1]
                + acc[r][2]*acc[r][2] + acc[r][3]*acc[r][3];
        #pragma unroll
        for (int off = 1; off < 16; off <<= 1)
            v += __shfl_xor_sync(0xffffffffu, v, off);
        ss[r] = v;
    }

    if (m != 2) {
        const float alpha = (m == 0) ? 2.0f / (scale[0] + EPSF) : 1.0f;
        const float tfac  = (m == 0) ? -alpha : 1.0f;
        float* base = ((m == 0) ? g_Q : g_K) + (size_t)(b * H_ + h) * PAD_ * N_;
        #pragma unroll
        for (int r = 0; r < 4; ++r) {
            #pragma unroll
            for (int c = 0; c < 4; ++c)
                base[(size_t)(c0 + c + 1) * N_ + (n0 + r0 + r)] = alpha * acc[r][c];
        }
        if (tx == 0) {
            #pragma unroll
            for (int r = 0; r < 4; ++r)
                base[n0 + r0 + r] = tfac * sqrtf(1.0f + ss[r]);
        }
        // zero pad rows d = 65..67
        for (int idx = tid; idx < 3 * 64; idx += 256) {
            int d = 65 + (idx >> 6), j = idx & 63;
            base[(size_t)d * N_ + n0 + j] = 0.0f;
        }
    } else {
        float* base = g_V + ((size_t)(b * H_ + h) * N_ + n0) * PAD_;
        #pragma unroll
        for (int r = 0; r < 4; ++r) {
            #pragma unroll
            for (int c = 0; c < 4; ++c)
                base[(size_t)(r0 + r) * PAD_ + (c0 + c + 1)] = acc[r][c];
        }
        if (tx == 0) {
            #pragma unroll
            for (int r = 0; r < 4; ++r)
                base[(size_t)(r0 + r) * PAD_] = sqrtf(1.0f + ss[r]);
        }
        for (int idx = tid; idx < 3 * 64; idx += 256) {
            int p = idx >> 6, j = idx & 63;
            base[(size_t)j * PAD_ + 65 + p] = 0.0f;
        }
    }
}

// ---------------------------------------------------------------------------
// Kernel 2: flash attention + per-head Lorentz midpoint normalization.
// grid (N/64, H, B), block 256.  16x16 thread map, 4x4 register tile.
// ---------------------------------------------------------------------------
__global__ __launch_bounds__(256) void attn_kernel()
{
    extern __shared__ float sm[];
    float* Qt = sm;                  // [68][64]  d-major
    float* Kt = Qt + PAD_ * 64;      // [68][64]  d-major       (off 4352)
    float* Vs = Kt + PAD_ * 64;      // [64][68]  row-major     (off 8704)
    float* Ps = Vs + 64 * PAD_;      // [64][68]  probs         (off 13056)

    const int tid = threadIdx.x;
    const int tx = tid & 15, ty = tid >> 4;
    const int n0 = blockIdx.x * 64;
    const int h  = blockIdx.y, b = blockIdx.z;
    const int bh = b * H_ + h;

    const float* Qg = g_Q + (size_t)bh * PAD_ * N_;
    const float* Kg = g_K + (size_t)bh * PAD_ * N_;
    const float* Vg = g_V + (size_t)bh * N_ * PAD_;

    // load Q tile (68 rows x 64)
    for (int idx = tid; idx < PAD_ * 16; idx += 256) {
        int d = idx >> 4, f = (idx & 15) << 2;
        *(float4*)&Qt[(d << 6) + f] = *(const float4*)&Qg[(size_t)d * N_ + n0 + f];
    }

    const int r0 = ty * 4, c0 = tx * 4;
    float O[4][4] = {};
    float Oe[4]   = {};   // spatial dim 64 (redundant across tx lanes)
    float mx[4] = {-INFINITY, -INFINITY, -INFINITY, -INFINITY};
    float l[4]  = {};

    for (int kt = 0; kt < NT_; ++kt) {
        __syncthreads();   // previous PV reads done before overwriting tiles
        const int kn = kt * 64;
        for (int idx = tid; idx < PAD_ * 16; idx += 256) {
            int d = idx >> 4, f = (idx & 15) << 2;
            *(float4*)&Kt[(d << 6) + f] = *(const float4*)&Kg[(size_t)d * N_ + kn + f];
        }
        for (int idx = tid; idx < 64 * 17; idx += 256) {
            int j = idx / 17, f = (idx - j * 17) << 2;
            *(float4*)&Vs[j * PAD_ + f] = *(const float4*)&Vg[((size_t)kn + j) * PAD_ + f];
        }
        __syncthreads();

        // S = Q~^T K  (reduce over 68 dims; pad rows are zero)
        float s[4][4] = {};
        #pragma unroll 4
        for (int d = 0; d < PAD_; ++d) {
            float4 a4 = *(const float4*)&Qt[(d << 6) + r0];
            float4 k4 = *(const float4*)&Kt[(d << 6) + c0];
            s[0][0] = fmaf(a4.x, k4.x, s[0][0]); s[0][1] = fmaf(a4.x, k4.y, s[0][1]);
            s[0][2] = fmaf(a4.x, k4.z, s[0][2]); s[0][3] = fmaf(a4.x, k4.w, s[0][3]);
            s[1][0] = fmaf(a4.y, k4.x, s[1][0]); s[1][1] = fmaf(a4.y, k4.y, s[1][1]);
            s[1][2] = fmaf(a4.y, k4.z, s[1][2]); s[1][3] = fmaf(a4.y, k4.w, s[1][3]);
            s[2][0] = fmaf(a4.z, k4.x, s[2][0]); s[2][1] = fmaf(a4.z, k4.y, s[2][1]);
            s[2][2] = fmaf(a4.z, k4.z, s[2][2]); s[2][3] = fmaf(a4.z, k4.w, s[2][3]);
            s[3][0] = fmaf(a4.w, k4.x, s[3][0]); s[3][1] = fmaf(a4.w, k4.y, s[3][1]);
            s[3][2] = fmaf(a4.w, k4.z, s[3][2]); s[3][3] = fmaf(a4.w, k4.w, s[3][3]);
        }

        // online softmax (row stats reduced over 16 tx lanes)
        #pragma unroll
        for (int r = 0; r < 4; ++r) {
            float rm = fmaxf(fmaxf(s[r][0], s[r][1]), fmaxf(s[r][2], s[r][3]));
            #pragma unroll
            for (int off = 1; off < 16; off <<= 1)
                rm = fmaxf(rm, __shfl_xor_sync(0xffffffffu, rm, off));
            float mnew = fmaxf(mx[r], rm);
            float corr = __expf(mx[r] - mnew);
            mx[r] = mnew;
            float rs = 0.0f;
            #pragma unroll
            for (int c = 0; c < 4; ++c) {
                s[r][c] = __expf(s[r][c] - mnew);
                rs += s[r][c];
            }
            #pragma unroll
            for (int off = 1; off < 16; off <<= 1)
                rs += __shfl_xor_sync(0xffffffffu, rs, off);
            l[r] = l[r] * corr + rs;
            #pragma unroll
            for (int c = 0; c < 4; ++c) O[r][c] *= corr;
            Oe[r] *= corr;
            *(float4*)&Ps[(r0 + r) * PAD_ + c0] = make_float4(s[r][0], s[r][1], s[r][2], s[r][3]);
        }
        __syncthreads();

        // O += P V
        #pragma unroll 2
        for (int j = 0; j < 64; ++j) {
            float4 v4 = *(const float4*)&Vs[j * PAD_ + c0];
            float ve  = Vs[j * PAD_ + 64];  // broadcast
            float p0 = Ps[(r0 + 0) * PAD_ + j];
            float p1 = Ps[(r0 + 1) * PAD_ + j];
            float p2 = Ps[(r0 + 2) * PAD_ + j];
            float p3 = Ps[(r0 + 3) * PAD_ + j];
            O[0][0] = fmaf(p0, v4.x, O[0][0]); O[0][1] = fmaf(p0, v4.y, O[0][1]);
            O[0][2] = fmaf(p0, v4.z, O[0][2]); O[0][3] = fmaf(p0, v4.w, O[0][3]);
            O[1][0] = fmaf(p1, v4.x, O[1][0]); O[1][1] = fmaf(p1, v4.y, O[1][1]);
            O[1][2] = fmaf(p1, v4.z, O[1][2]); O[1][3] = fmaf(p1, v4.w, O[1][3]);
            O[2][0] = fmaf(p2, v4.x, O[2][0]); O[2][1] = fmaf(p2, v4.y, O[2][1]);
            O[2][2] = fmaf(p2, v4.z, O[2][2]); O[2][3] = fmaf(p2, v4.w, O[2][3]);
            O[3][0] = fmaf(p3, v4.x, O[3][0]); O[3][1] = fmaf(p3, v4.y, O[3][1]);
            O[3][2] = fmaf(p3, v4.z, O[3][2]); O[3][3] = fmaf(p3, v4.w, O[3][3]);
            Oe[0] = fmaf(p0, ve, Oe[0]); Oe[1] = fmaf(p1, ve, Oe[1]);
            Oe[2] = fmaf(p2, ve, Oe[2]); Oe[3] = fmaf(p3, ve, Oe[3]);
        }
    }

    // epilogue: mu = O / l ; Lorentz-normalize per row ; write Mid
    #pragma unroll
    for (int r = 0; r < 4; ++r) {
        float il = 1.0f / l[r];
        #pragma unroll
        for (int c = 0; c < 4; ++c) O[r][c] *= il;
        Oe[r] *= il;
        float sgn0 = (c0 == 0) ? -1.0f : 1.0f;  // global dim 0 is Lorentz time
        float v = sgn0 * O[r][0]*O[r][0] + O[r][1]*O[r][1]
                + O[r][2]*O[r][2] + O[r][3]*O[r][3];
        if (tx == 0) v += Oe[r] * Oe[r];        // dim 64, counted once
        #pragma unroll
        for (int off = 1; off < 16; off <<= 1)
            v += __shfl_xor_sync(0xffffffffu, v, off);
        float id = rsqrtf(fmaxf(-v, EPSF));
        #pragma unroll
        for (int c = 0; c < 4; ++c) O[r][c] *= id;
        Oe[r] *= id;

        float* dst = g_Mid + ((size_t)(b * N_ + n0 + r0 + r) * H_ + h) * PAD_;
        *(float4*)&dst[c0] = make_float4(O[r][0], O[r][1], O[r][2], O[r][3]);
        if (tx == 0) dst[64] = Oe[r];
    }
}

// ---------------------------------------------------------------------------
// Kernel 3: mean over heads, Lorentz-normalize, re-lift to curvature C_OUT.
// one warp per (b,n); lanes cover ambient dims (d, d+32, d+64).
// ---------------------------------------------------------------------------
__global__ __launch_bounds__(256) void merge_kernel(float* __restrict__ out)
{
    const int gw = (blockIdx.x * blockDim.x + threadIdx.x) >> 5;
    const int lane = threadIdx.x & 31;
    if (gw >= B_ * N_) return;

    const float* base = g_Mid + (size_t)gw * H_ * PAD_;
    float avg[3] = {0.0f, 0.0f, 0.0f};
    {
        int k = 0;
        for (int d = lane; d < AMB_; d += 32, ++k) {
            float sacc = 0.0f;
            #pragma unroll
            for (int hh = 0; hh < H_; ++hh) sacc += base[hh * PAD_ + d];
            avg[k] = sacc * (1.0f / H_);
        }
    }
    // Lorentz inner of avg
    float part = 0.0f;
    {
        int k = 0;
        for (int d = lane; d < AMB_; d += 32, ++k)
            part += ((d == 0) ? -1.0f : 1.0f) * avg[k] * avg[k];
    }
    #pragma unroll
    for (int off = 1; off < 32; off <<= 1)
        part += __shfl_xor_sync(0xffffffffu, part, off);
    const float id = rsqrtf(fmaxf(-part, EPSF));

    // spatial norm of the normalized point (dims >= 1)
    float p2 = 0.0f;
    {
        int k = 0;
        for (int d = lane; d < AMB_; d += 32, ++k) {
            if (d > 0) { float v = avg[k] * id; p2 += v * v; }
        }
    }
    #pragma unroll
    for (int off = 1; off < 32; off <<= 1)
        p2 += __shfl_xor_sync(0xffffffffu, p2, off);
    const float t = sqrtf(1.0f + p2);

    float* o = out + (size_t)gw * AMB_;
    {
        int k = 0;
        for (int d = lane; d < AMB_; d += 32, ++k)
            o[d] = (d == 0) ? t : avg[k] * id;
    }
}

// ---------------------------------------------------------------------------
extern "C" void kernel_launch(void* const* d_in, const int* in_sizes, int n_in,
                              void* d_out, int out_size)
{
    const float* x     = (const float*)d_in[0];
    const float* Wq    = (const float*)d_in[1];
    const float* Wk    = (const float*)d_in[2];
    const float* Wv    = (const float*)d_in[3];
    const float* bq    = (const float*)d_in[4];
    const float* bk    = (const float*)d_in[5];
    const float* bv    = (const float*)d_in[6];
    const float* scale = (const float*)d_in[7];
    (void)d_in; (void)in_sizes; (void)n_in; (void)out_size;

    const int smem1 = (XST_ + DIN_ * PAD_) * (int)sizeof(float);        // 68640
    const int smem2 = 4 * PAD_ * 64 * (int)sizeof(float);               // 69632

    cudaFuncSetAttribute(proj_kernel, cudaFuncAttributeMaxDynamicSharedMemorySize, smem1);
    cudaFuncSetAttribute(attn_kernel, cudaFuncAttributeMaxDynamicSharedMemorySize, smem2);

    proj_kernel<<<dim3(NT_, H_, B_ * 3), 256, smem1>>>(x, Wq, Wk, Wv, bq, bk, bv, scale);
    attn_kernel<<<dim3(NT_, H_, B_), 256, smem2>>>();
    merge_kernel<<<(B_ * N_ * 32) / 256, 256>>>((float*)d_out);
}

// round 6
// speedup vs baseline: 3.0623x; 3.0623x over previous
#include <cuda_runtime.h>
#include <cuda_bf16.h>
#include <math.h>
#include <cstdint>

// ---------------------------------------------------------------------------
// HyperbolicFullAttention — FA2-style bf16 mma.sync flash attention.
// (tcgen05 unavailable: harness PTX target is compute_103 w/o 'a' features)
//
// score = alpha*(qs.ks) - alpha*q0*(k0-1) + const(row)   [alpha=2/(scale+eps)]
// li <= -1 => centered scores bounded above ~0: softmax needs NO max pass.
// log2e folded into alpha -> softmax weight = ex2(score_log2).
// mu0 = 1 + sum_j w_j*(v0_j - 1) / l.  MMA handles only 64 spatial dims.
// ---------------------------------------------------------------------------

#define B_    4
#define N_    2048
#define DIN_  129
#define H_    8
#define AMB_  65
#define PAD_  68
#define EPSF  1e-7f
#define XST_  8388
#define LOG2E 1.4426950408889634f

__device__ __align__(16) __nv_bfloat16 g_Qs[(size_t)B_*H_*N_*64];  // alpha*log2e*qs (bh,n,d)
__device__ __align__(16) __nv_bfloat16 g_Ks[(size_t)B_*H_*N_*64];  // ks (bh,n,d)
__device__ __align__(16) __nv_bfloat16 g_Vt[(size_t)B_*H_*64*N_];  // vs d-major (bh,d,n)
__device__ __align__(16) float g_q0a[(size_t)B_*H_*N_];            // alpha*log2e*q0
__device__ __align__(16) float g_ek [(size_t)B_*H_*N_];            // k0-1
__device__ __align__(16) float g_ev [(size_t)B_*H_*N_];            // v0-1
__device__ __align__(16) float g_Mid[(size_t)B_*N_*H_*PAD_];       // (b,n,h,68)

__device__ __forceinline__ uint32_t smem_u32(const void* p) {
    uint32_t a;
    asm("{ .reg .u64 t; cvta.to.shared.u64 t, %1; cvt.u32.u64 %0, t; }" : "=r"(a) : "l"(p));
    return a;
}
#define SWZ128(x) ((x) ^ (((x) >> 3) & 0x70))

__device__ __forceinline__ void ldsm_x4(uint32_t& r0, uint32_t& r1, uint32_t& r2, uint32_t& r3, uint32_t a) {
    asm volatile("ldmatrix.sync.aligned.m8n8.x4.shared.b16 {%0,%1,%2,%3}, [%4];"
        : "=r"(r0), "=r"(r1), "=r"(r2), "=r"(r3) : "r"(a));
}
__device__ __forceinline__ void mma_bf16(float* c, const uint32_t* a, uint32_t b0, uint32_t b1) {
    asm volatile("mma.sync.aligned.m16n8k16.row.col.f32.bf16.bf16.f32 "
        "{%0,%1,%2,%3}, {%4,%5,%6,%7}, {%8,%9}, {%0,%1,%2,%3};"
        : "+f"(c[0]), "+f"(c[1]), "+f"(c[2]), "+f"(c[3])
        : "r"(a[0]), "r"(a[1]), "r"(a[2]), "r"(a[3]), "r"(b0), "r"(b1));
}
__device__ __forceinline__ float ex2f(float x) {
    float y; asm("ex2.approx.f32 %0, %1;" : "=f"(y) : "f"(x)); return y;
}

// ---------------------------------------------------------------------------
// Kernel 1: projection + lift (fp32 core, bf16 outputs).
// grid (N/64, H, B*3); 256 threads, 16x16 map, 4x4 tiles.
// ---------------------------------------------------------------------------
__global__ __launch_bounds__(256) void proj_kernel(
    const float* __restrict__ x,
    const float* __restrict__ Wq, const float* __restrict__ Wk, const float* __restrict__ Wv,
    const float* __restrict__ bq, const float* __restrict__ bk, const float* __restrict__ bv,
    const float* __restrict__ scale)
{
    extern __shared__ float sm[];
    float* xsT = sm;            // [129][65]
    float* Ws  = sm + XST_;     // [129][68]

    const int tid = threadIdx.x;
    const int tx = tid & 15, ty = tid >> 4;
    const int n0 = blockIdx.x * 64;
    const int h  = blockIdx.y;
    const int b  = blockIdx.z / 3;
    const int m  = blockIdx.z % 3;
    const int bh = b * H_ + h;

    const float* W    = (m == 0) ? Wq : (m == 1) ? Wk : Wv;
    const float* bias = (m == 0) ? bq : (m == 1) ? bk : bv;

    const float* xbase = x + ((size_t)b * N_ + n0) * DIN_;
    for (int idx = tid; idx < 64 * DIN_; idx += 256) {
        int r = idx / DIN_;
        int i = idx - r * DIN_;
        xsT[i * 65 + r] = xbase[idx];
    }
    const float* Wh = W + (size_t)h * DIN_ * 64;
    for (int idx = tid; idx < DIN_ * 64; idx += 256) {
        int i = idx >> 6, d = idx & 63;
        Ws[i * PAD_ + d] = Wh[idx];
    }
    __syncthreads();

    const int r0 = ty * 4, c0 = tx * 4;
    float acc[4][4] = {};
    for (int i = 0; i < DIN_; ++i) {
        const float* xr = &xsT[i * 65 + r0];
        float a0 = xr[0], a1 = xr[1], a2 = xr[2], a3 = xr[3];
        float4 w4 = *(const float4*)&Ws[i * PAD_ + c0];
        acc[0][0] = fmaf(a0, w4.x, acc[0][0]); acc[0][1] = fmaf(a0, w4.y, acc[0][1]);
        acc[0][2] = fmaf(a0, w4.z, acc[0][2]); acc[0][3] = fmaf(a0, w4.w, acc[0][3]);
        acc[1][0] = fmaf(a1, w4.x, acc[1][0]); acc[1][1] = fmaf(a1, w4.y, acc[1][1]);
        acc[1][2] = fmaf(a1, w4.z, acc[1][2]); acc[1][3] = fmaf(a1, w4.w, acc[1][3]);
        acc[2][0] = fmaf(a2, w4.x, acc[2][0]); acc[2][1] = fmaf(a2, w4.y, acc[2][1]);
        acc[2][2] = fmaf(a2, w4.z, acc[2][2]); acc[2][3] = fmaf(a2, w4.w, acc[2][3]);
        acc[3][0] = fmaf(a3, w4.x, acc[3][0]); acc[3][1] = fmaf(a3, w4.y, acc[3][1]);
        acc[3][2] = fmaf(a3, w4.z, acc[3][2]); acc[3][3] = fmaf(a3, w4.w, acc[3][3]);
    }
    const float* bhh = &bias[h * 64 + c0];
    float b0 = bhh[0], b1 = bhh[1], b2 = bhh[2], b3 = bhh[3];
    #pragma unroll
    for (int r = 0; r < 4; ++r) {
        acc[r][0] += b0; acc[r][1] += b1; acc[r][2] += b2; acc[r][3] += b3;
    }
    float ss[4];
    #pragma unroll
    for (int r = 0; r < 4; ++r) {
        float v = acc[r][0]*acc[r][0] + acc[r][1]*acc[r][1]
                + acc[r][2]*acc[r][2] + acc[r][3]*acc[r][3];
        #pragma unroll
        for (int off = 1; off < 16; off <<= 1)
            v += __shfl_xor_sync(0xffffffffu, v, off);
        ss[r] = v;
    }

    if (m == 0) {
        const float alpha = (2.0f / (scale[0] + EPSF)) * LOG2E;
        __nv_bfloat16* base = g_Qs + (size_t)bh * N_ * 64;
        #pragma unroll
        for (int r = 0; r < 4; ++r) {
            size_t ro = (size_t)(n0 + r0 + r) * 64 + c0;
            *(__nv_bfloat162*)&base[ro]     = __floats2bfloat162_rn(alpha*acc[r][0], alpha*acc[r][1]);
            *(__nv_bfloat162*)&base[ro + 2] = __floats2bfloat162_rn(alpha*acc[r][2], alpha*acc[r][3]);
        }
        if (tx == 0) {
            float* qa = g_q0a + (size_t)bh * N_ + n0;
            #pragma unroll
            for (int r = 0; r < 4; ++r)
                qa[r0 + r] = alpha * sqrtf(1.0f + ss[r]);
        }
    } else if (m == 1) {
        __nv_bfloat16* base = g_Ks + (size_t)bh * N_ * 64;
        #pragma unroll
        for (int r = 0; r < 4; ++r) {
            size_t ro = (size_t)(n0 + r0 + r) * 64 + c0;
            *(__nv_bfloat162*)&base[ro]     = __floats2bfloat162_rn(acc[r][0], acc[r][1]);
            *(__nv_bfloat162*)&base[ro + 2] = __floats2bfloat162_rn(acc[r][2], acc[r][3]);
        }
        if (tx == 0) {
            float* ea = g_ek + (size_t)bh * N_ + n0;
            #pragma unroll
            for (int r = 0; r < 4; ++r)
                ea[r0 + r] = sqrtf(1.0f + ss[r]) - 1.0f;
        }
    } else {
        __nv_bfloat16* base = g_Vt + (size_t)bh * 64 * N_;
        #pragma unroll
        for (int r = 0; r < 4; ++r)
            #pragma unroll
            for (int c = 0; c < 4; ++c)
                base[(size_t)(c0 + c) * N_ + (n0 + r0 + r)] = __float2bfloat16(acc[r][c]);
        if (tx == 0) {
            float* ea = g_ev + (size_t)bh * N_ + n0;
            #pragma unroll
            for (int r = 0; r < 4; ++r)
                ea[r0 + r] = sqrtf(1.0f + ss[r]) - 1.0f;
        }
    }
}

// ---------------------------------------------------------------------------
// Kernel 2: mma.sync flash attention. grid (16, 32), 256 threads (8 warps).
// Warp w owns query rows m0=w*16 (one m16 block). Key tiles of 128.
// SMEM: ek[128] | ev[128] | Q[128x128B SW128] | K[128x128B SW128] |
//       V 2 panels [64x128B SW128]
// ---------------------------------------------------------------------------
#define AOFF_EK 0
#define AOFF_EV 512
#define AOFF_Q  1024
#define AOFF_K  (AOFF_Q + 16384)
#define AOFF_V  (AOFF_K + 16384)
#define SMEM_ATTN (AOFF_V + 16384)

__global__ __launch_bounds__(256) void attn_kernel()
{
    extern __shared__ char smc[];
    float* ek_s = (float*)(smc + AOFF_EK);
    float* ev_s = (float*)(smc + AOFF_EV);
    char*  Qs   = smc + AOFF_Q;
    char*  Ks   = smc + AOFF_K;
    char*  Vs   = smc + AOFF_V;

    const int tid  = threadIdx.x;
    const int wid  = tid >> 5, lane = tid & 31;
    const int bh   = blockIdx.y;
    const int n0   = blockIdx.x * 128;
    const int m0   = wid * 16;
    const int g    = lane >> 2, tig = lane & 3;
    const int r    = lane & 7, grp = lane >> 3;

    const uint32_t Qsb = smem_u32(Qs), Ksb = smem_u32(Ks), Vsb = smem_u32(Vs);

    // stage Q tile (128 rows x 128B, SW128)
    const __nv_bfloat16* Qg = g_Qs + ((size_t)bh * N_ + n0) * 64;
    for (int i = tid; i < 1024; i += 256) {
        int row = i >> 3, c = i & 7;
        uint4 v = *(const uint4*)((const char*)Qg + row * 128 + c * 16);
        *(uint4*)(Qs + SWZ128(row * 128 + c * 16)) = v;
    }
    __syncthreads();

    // Q fragments, resident across the whole key loop
    uint32_t qa[4][4];
    {
        int qrow = m0 + r + (grp & 1) * 8;
        int cb   = (grp >> 1) * 16;
        #pragma unroll
        for (int t = 0; t < 4; ++t)
            ldsm_x4(qa[t][0], qa[t][1], qa[t][2], qa[t][3],
                    Qsb + SWZ128(qrow * 128 + t * 32 + cb));
    }

    const float q0a0 = g_q0a[(size_t)bh * N_ + n0 + m0 + g];
    const float q0a1 = g_q0a[(size_t)bh * N_ + n0 + m0 + g + 8];
    float l0 = 0.f, l1 = 0.f, pe0 = 0.f, pe1 = 0.f;
    float oacc[8][4] = {};

    for (int kt = 0; kt < 16; ++kt) {
        if (kt) __syncthreads();
        const int kn = kt * 128;
        const __nv_bfloat16* Kg = g_Ks + ((size_t)bh * N_ + kn) * 64;
        for (int i = tid; i < 1024; i += 256) {
            int row = i >> 3, c = i & 7;
            uint4 v = *(const uint4*)((const char*)Kg + row * 128 + c * 16);
            *(uint4*)(Ks + SWZ128(row * 128 + c * 16)) = v;
        }
        const __nv_bfloat16* Vg = g_Vt + (size_t)bh * 64 * N_ + kn;
        for (int i = tid; i < 1024; i += 256) {
            int d = i >> 4, c = i & 15;
            uint4 v = *(const uint4*)((const char*)(Vg + (size_t)d * N_) + c * 16);
            int panel = c >> 3, local = d * 128 + (c & 7) * 16;
            *(uint4*)(Vs + panel * 8192 + SWZ128(local)) = v;
        }
        if (tid < 128) {
            ek_s[tid] = g_ek[(size_t)bh * N_ + kn + tid];
            ev_s[tid] = g_ev[(size_t)bh * N_ + kn + tid];
        }
        __syncthreads();

        // ---- S = Q K^T : 16 n8-tiles over 128 keys, K=64 (4 k16 steps) ----
        float sacc[16][4];
        #pragma unroll
        for (int nt = 0; nt < 16; ++nt)
            { sacc[nt][0] = 0.f; sacc[nt][1] = 0.f; sacc[nt][2] = 0.f; sacc[nt][3] = 0.f; }
        #pragma unroll
        for (int t = 0; t < 4; ++t) {
            #pragma unroll
            for (int ntp = 0; ntp < 8; ++ntp) {
                int rowb = (2 * ntp + (grp >> 1)) * 8 + r;
                uint32_t b0, b1, b2, b3;
                ldsm_x4(b0, b1, b2, b3,
                        Ksb + SWZ128(rowb * 128 + t * 32 + (grp & 1) * 16));
                mma_bf16(sacc[2 * ntp],     qa[t], b0, b1);
                mma_bf16(sacc[2 * ntp + 1], qa[t], b2, b3);
            }
        }

        // ---- softmax (no max pass) + pack P fragments ----
        uint32_t pa[8][4];
        #pragma unroll
        for (int nt = 0; nt < 16; ++nt) {
            int col = nt * 8 + 2 * tig;
            float ekc0 = ek_s[col], ekc1 = ek_s[col + 1];
            float evc0 = ev_s[col], evc1 = ev_s[col + 1];
            float e00 = ex2f(fmaf(-q0a0, ekc0, sacc[nt][0]));
            float e01 = ex2f(fmaf(-q0a0, ekc1, sacc[nt][1]));
            float e10 = ex2f(fmaf(-q0a1, ekc0, sacc[nt][2]));
            float e11 = ex2f(fmaf(-q0a1, ekc1, sacc[nt][3]));
            l0 += e00 + e01; l1 += e10 + e11;
            pe0 = fmaf(e00, evc0, fmaf(e01, evc1, pe0));
            pe1 = fmaf(e10, evc0, fmaf(e11, evc1, pe1));
            __nv_bfloat162 t0 = __floats2bfloat162_rn(e00, e01);
            __nv_bfloat162 t1 = __floats2bfloat162_rn(e10, e11);
            int kt8 = nt >> 1, half = nt & 1;
            pa[kt8][2 * half]     = *(uint32_t*)&t0;
            pa[kt8][2 * half + 1] = *(uint32_t*)&t1;
        }

        // ---- O += P V : 8 dim-tiles (64), K=128 (8 k16 steps) ----
        #pragma unroll
        for (int kt8 = 0; kt8 < 8; ++kt8) {
            int panel = kt8 >> 2;
            int kb = (kt8 & 3) * 32;
            #pragma unroll
            for (int dtp = 0; dtp < 4; ++dtp) {
                int rowd = (2 * dtp + (grp >> 1)) * 8 + r;
                uint32_t b0, b1, b2, b3;
                ldsm_x4(b0, b1, b2, b3,
                        Vsb + panel * 8192 + SWZ128(rowd * 128 + kb + (grp & 1) * 16));
                mma_bf16(oacc[2 * dtp],     pa[kt8], b0, b1);
                mma_bf16(oacc[2 * dtp + 1], pa[kt8], b2, b3);
            }
        }
    }

    // ---- epilogue: quad-reduce row stats, Lorentz-normalize, write Mid ----
    #pragma unroll
    for (int off = 1; off < 4; off <<= 1) {
        l0  += __shfl_xor_sync(0xffffffffu, l0,  off);
        l1  += __shfl_xor_sync(0xffffffffu, l1,  off);
        pe0 += __shfl_xor_sync(0xffffffffu, pe0, off);
        pe1 += __shfl_xor_sync(0xffffffffu, pe1, off);
    }
    const float il0 = 1.0f / l0, il1 = 1.0f / l1;
    const float mu00 = 1.0f + pe0 * il0, mu01 = 1.0f + pe1 * il1;
    float mr0[16], mr1[16], ss0 = 0.f, ss1 = 0.f;
    #pragma unroll
    for (int dt = 0; dt < 8; ++dt) {
        #pragma unroll
        for (int j = 0; j < 2; ++j) {
            float v0 = oacc[dt][j]     * il0;
            float v1 = oacc[dt][2 + j] * il1;
            mr0[dt * 2 + j] = v0; ss0 = fmaf(v0, v0, ss0);
            mr1[dt * 2 + j] = v1; ss1 = fmaf(v1, v1, ss1);
        }
    }
    #pragma unroll
    for (int off = 1; off < 4; off <<= 1) {
        ss0 += __shfl_xor_sync(0xffffffffu, ss0, off);
        ss1 += __shfl_xor_sync(0xffffffffu, ss1, off);
    }
    const float id0 = rsqrtf(fmaxf(mu00 * mu00 - ss0, EPSF));
    const float id1 = rsqrtf(fmaxf(mu01 * mu01 - ss1, EPSF));

    const int b = bh >> 3, h = bh & 7;
    float* d0 = g_Mid + ((size_t)(b * N_ + n0 + m0 + g)     * H_ + h) * PAD_;
    float* d1 = g_Mid + ((size_t)(b * N_ + n0 + m0 + g + 8) * H_ + h) * PAD_;
    #pragma unroll
    for (int dt = 0; dt < 8; ++dt) {
        int col = dt * 8 + 2 * tig;
        d0[1 + col]     = mr0[dt * 2]     * id0;
        d0[1 + col + 1] = mr0[dt * 2 + 1] * id0;
        d1[1 + col]     = mr1[dt * 2]     * id1;
        d1[1 + col + 1] = mr1[dt * 2 + 1] * id1;
    }
    if (tig == 0) { d0[0] = mu00 * id0; d1[0] = mu01 * id1; }
}

// ---------------------------------------------------------------------------
// Kernel 3: mean over heads, Lorentz-normalize, re-lift.
// ---------------------------------------------------------------------------
__global__ __launch_bounds__(256) void merge_kernel(float* __restrict__ out)
{
    const int gw = (blockIdx.x * blockDim.x + threadIdx.x) >> 5;
    const int lane = threadIdx.x & 31;
    if (gw >= B_ * N_) return;

    const float* base = g_Mid + (size_t)gw * H_ * PAD_;
    float avg[3] = {0.0f, 0.0f, 0.0f};
    {
        int k = 0;
        for (int d = lane; d < AMB_; d += 32, ++k) {
            float sacc = 0.0f;
            #pragma unroll
            for (int hh = 0; hh < H_; ++hh) sacc += base[hh * PAD_ + d];
            avg[k] = sacc * (1.0f / H_);
        }
    }
    float part = 0.0f;
    {
        int k = 0;
        for (int d = lane; d < AMB_; d += 32, ++k)
            part += ((d == 0) ? -1.0f : 1.0f) * avg[k] * avg[k];
    }
    #pragma unroll
    for (int off = 1; off < 32; off <<= 1)
        part += __shfl_xor_sync(0xffffffffu, part, off);
    const float id = rsqrtf(fmaxf(-part, EPSF));

    float p2 = 0.0f;
    {
        int k = 0;
        for (int d = lane; d < AMB_; d += 32, ++k) {
            if (d > 0) { float v = avg[k] * id; p2 += v * v; }
        }
    }
    #pragma unroll
    for (int off = 1; off < 32; off <<= 1)
        p2 += __shfl_xor_sync(0xffffffffu, p2, off);
    const float t = sqrtf(1.0f + p2);

    float* o = out + (size_t)gw * AMB_;
    {
        int k = 0;
        for (int d = lane; d < AMB_; d += 32, ++k)
            o[d] = (d == 0) ? t : avg[k] * id;
    }
}

// ---------------------------------------------------------------------------
extern "C" void kernel_launch(void* const* d_in, const int* in_sizes, int n_in,
                              void* d_out, int out_size)
{
    const float* x     = (const float*)d_in[0];
    const float* Wq    = (const float*)d_in[1];
    const float* Wk    = (const float*)d_in[2];
    const float* Wv    = (const float*)d_in[3];
    const float* bq    = (const float*)d_in[4];
    const float* bk    = (const float*)d_in[5];
    const float* bv    = (const float*)d_in[6];
    const float* scale = (const float*)d_in[7];
    (void)in_sizes; (void)n_in; (void)out_size;

    const int smem1 = (XST_ + DIN_ * PAD_) * (int)sizeof(float);   // 68640
    const int smem2 = SMEM_ATTN;                                   // 50176

    cudaFuncSetAttribute(proj_kernel, cudaFuncAttributeMaxDynamicSharedMemorySize, smem1);
    cudaFuncSetAttribute(attn_kernel, cudaFuncAttributeMaxDynamicSharedMemorySize, smem2);

    proj_kernel<<<dim3(N_ / 64, H_, B_ * 3), 256, smem1>>>(x, Wq, Wk, Wv, bq, bk, bv, scale);
    attn_kernel<<<dim3(N_ / 128, B_ * H_), 256, smem2>>>();
    merge_kernel<<<(B_ * N_ * 32) / 256, 256>>>((float*)d_out);
}

// round 13
// speedup vs baseline: 5.1116x; 1.6692x over previous
#include <cuda_runtime.h>
#include <cuda_bf16.h>
#include <math.h>
#include <cstdint>

// ---------------------------------------------------------------------------
// HyperbolicFullAttention — FA2-style bf16 mma.sync flash attention, v2:
//   * two 64-key halves per 128-key tile -> sacc halved -> <=128 regs
//   * __launch_bounds__(256,2) -> 2 CTAs/SM (4 warps/SMSP)
//   * cp.async double-buffered K/V/ek/ev staging (overlaps with compute)
//
// score = alpha*(qs.ks) - alpha*q0*(k0-1) + const(row)   [alpha=2/(scale+eps)]
// li <= -1 => centered scores bounded: softmax needs NO max pass.
// log2e folded into alpha -> weight = ex2(score_log2).
// mu0 = 1 + sum_j w_j*(v0_j-1)/l.  MMA covers only the 64 spatial dims.
// ---------------------------------------------------------------------------

#define B_    4
#define N_    2048
#define DIN_  129
#define H_    8
#define AMB_  65
#define PAD_  68
#define EPSF  1e-7f
#define XST_  8388
#define LOG2E 1.4426950408889634f

__device__ __align__(16) __nv_bfloat16 g_Qs[(size_t)B_*H_*N_*64];  // alpha*log2e*qs (bh,n,d)
__device__ __align__(16) __nv_bfloat16 g_Ks[(size_t)B_*H_*N_*64];  // ks (bh,n,d)
__device__ __align__(16) __nv_bfloat16 g_Vt[(size_t)B_*H_*64*N_];  // vs d-major (bh,d,n)
__device__ __align__(16) float g_q0a[(size_t)B_*H_*N_];            // alpha*log2e*q0
__device__ __align__(16) float g_ek [(size_t)B_*H_*N_];            // k0-1
__device__ __align__(16) float g_ev [(size_t)B_*H_*N_];            // v0-1
__device__ __align__(16) float g_Mid[(size_t)B_*N_*H_*PAD_];       // (b,n,h,68)

__device__ __forceinline__ uint32_t smem_u32(const void* p) {
    uint32_t a;
    asm("{ .reg .u64 t; cvta.to.shared.u64 t, %1; cvt.u32.u64 %0, t; }" : "=r"(a) : "l"(p));
    return a;
}
#define SWZ128(x) ((x) ^ (((x) >> 3) & 0x70))

__device__ __forceinline__ void ldsm_x4(uint32_t& r0, uint32_t& r1, uint32_t& r2, uint32_t& r3, uint32_t a) {
    asm volatile("ldmatrix.sync.aligned.m8n8.x4.shared.b16 {%0,%1,%2,%3}, [%4];"
        : "=r"(r0), "=r"(r1), "=r"(r2), "=r"(r3) : "r"(a));
}
__device__ __forceinline__ void mma_bf16(float* c, const uint32_t* a, uint32_t b0, uint32_t b1) {
    asm volatile("mma.sync.aligned.m16n8k16.row.col.f32.bf16.bf16.f32 "
        "{%0,%1,%2,%3}, {%4,%5,%6,%7}, {%8,%9}, {%0,%1,%2,%3};"
        : "+f"(c[0]), "+f"(c[1]), "+f"(c[2]), "+f"(c[3])
        : "r"(a[0]), "r"(a[1]), "r"(a[2]), "r"(a[3]), "r"(b0), "r"(b1));
}
__device__ __forceinline__ float ex2f(float x) {
    float y; asm("ex2.approx.f32 %0, %1;" : "=f"(y) : "f"(x)); return y;
}
__device__ __forceinline__ void cp_async16(uint32_t dst, const void* src) {
    asm volatile("cp.async.cg.shared.global [%0], [%1], 16;" :: "r"(dst), "l"(src) : "memory");
}

// ---------------------------------------------------------------------------
// Kernel 1: projection + lift (fp32 core, bf16 outputs). Unchanged from R6.
// ---------------------------------------------------------------------------
__global__ __launch_bounds__(256) void proj_kernel(
    const float* __restrict__ x,
    const float* __restrict__ Wq, const float* __restrict__ Wk, const float* __restrict__ Wv,
    const float* __restrict__ bq, const float* __restrict__ bk, const float* __restrict__ bv,
    const float* __restrict__ scale)
{
    extern __shared__ float sm[];
    float* xsT = sm;            // [129][65]
    float* Ws  = sm + XST_;     // [129][68]

    const int tid = threadIdx.x;
    const int tx = tid & 15, ty = tid >> 4;
    const int n0 = blockIdx.x * 64;
    const int h  = blockIdx.y;
    const int b  = blockIdx.z / 3;
    const int m  = blockIdx.z % 3;
    const int bh = b * H_ + h;

    const float* W    = (m == 0) ? Wq : (m == 1) ? Wk : Wv;
    const float* bias = (m == 0) ? bq : (m == 1) ? bk : bv;

    const float* xbase = x + ((size_t)b * N_ + n0) * DIN_;
    for (int idx = tid; idx < 64 * DIN_; idx += 256) {
        int r = idx / DIN_;
        int i = idx - r * DIN_;
        xsT[i * 65 + r] = xbase[idx];
    }
    const float* Wh = W + (size_t)h * DIN_ * 64;
    for (int idx = tid; idx < DIN_ * 64; idx += 256) {
        int i = idx >> 6, d = idx & 63;
        Ws[i * PAD_ + d] = Wh[idx];
    }
    __syncthreads();

    const int r0 = ty * 4, c0 = tx * 4;
    float acc[4][4] = {};
    for (int i = 0; i < DIN_; ++i) {
        const float* xr = &xsT[i * 65 + r0];
        float a0 = xr[0], a1 = xr[1], a2 = xr[2], a3 = xr[3];
        float4 w4 = *(const float4*)&Ws[i * PAD_ + c0];
        acc[0][0] = fmaf(a0, w4.x, acc[0][0]); acc[0][1] = fmaf(a0, w4.y, acc[0][1]);
        acc[0][2] = fmaf(a0, w4.z, acc[0][2]); acc[0][3] = fmaf(a0, w4.w, acc[0][3]);
        acc[1][0] = fmaf(a1, w4.x, acc[1][0]); acc[1][1] = fmaf(a1, w4.y, acc[1][1]);
        acc[1][2] = fmaf(a1, w4.z, acc[1][2]); acc[1][3] = fmaf(a1, w4.w, acc[1][3]);
        acc[2][0] = fmaf(a2, w4.x, acc[2][0]); acc[2][1] = fmaf(a2, w4.y, acc[2][1]);
        acc[2][2] = fmaf(a2, w4.z, acc[2][2]); acc[2][3] = fmaf(a2, w4.w, acc[2][3]);
        acc[3][0] = fmaf(a3, w4.x, acc[3][0]); acc[3][1] = fmaf(a3, w4.y, acc[3][1]);
        acc[3][2] = fmaf(a3, w4.z, acc[3][2]); acc[3][3] = fmaf(a3, w4.w, acc[3][3]);
    }
    const float* bhh = &bias[h * 64 + c0];
    float b0 = bhh[0], b1 = bhh[1], b2 = bhh[2], b3 = bhh[3];
    #pragma unroll
    for (int r = 0; r < 4; ++r) {
        acc[r][0] += b0; acc[r][1] += b1; acc[r][2] += b2; acc[r][3] += b3;
    }
    float ss[4];
    #pragma unroll
    for (int r = 0; r < 4; ++r) {
        float v = acc[r][0]*acc[r][0] + acc[r][1]*acc[r][1]
                + acc[r][2]*acc[r][2] + acc[r][3]*acc[r][3];
        #pragma unroll
        for (int off = 1; off < 16; off <<= 1)
            v += __shfl_xor_sync(0xffffffffu, v, off);
        ss[r] = v;
    }

    if (m == 0) {
        const float alpha = (2.0f / (scale[0] + EPSF)) * LOG2E;
        __nv_bfloat16* base = g_Qs + (size_t)bh * N_ * 64;
        #pragma unroll
        for (int r = 0; r < 4; ++r) {
            size_t ro = (size_t)(n0 + r0 + r) * 64 + c0;
            *(__nv_bfloat162*)&base[ro]     = __floats2bfloat162_rn(alpha*acc[r][0], alpha*acc[r][1]);
            *(__nv_bfloat162*)&base[ro + 2] = __floats2bfloat162_rn(alpha*acc[r][2], alpha*acc[r][3]);
        }
        if (tx == 0) {
            float* qa = g_q0a + (size_t)bh * N_ + n0;
            #pragma unroll
            for (int r = 0; r < 4; ++r)
                qa[r0 + r] = alpha * sqrtf(1.0f + ss[r]);
        }
    } else if (m == 1) {
        __nv_bfloat16* base = g_Ks + (size_t)bh * N_ * 64;
        #pragma unroll
        for (int r = 0; r < 4; ++r) {
            size_t ro = (size_t)(n0 + r0 + r) * 64 + c0;
            *(__nv_bfloat162*)&base[ro]     = __floats2bfloat162_rn(acc[r][0], acc[r][1]);
            *(__nv_bfloat162*)&base[ro + 2] = __floats2bfloat162_rn(acc[r][2], acc[r][3]);
        }
        if (tx == 0) {
            float* ea = g_ek + (size_t)bh * N_ + n0;
            #pragma unroll
            for (int r = 0; r < 4; ++r)
                ea[r0 + r] = sqrtf(1.0f + ss[r]) - 1.0f;
        }
    } else {
        __nv_bfloat16* base = g_Vt + (size_t)bh * 64 * N_;
        #pragma unroll
        for (int r = 0; r < 4; ++r)
            #pragma unroll
            for (int c = 0; c < 4; ++c)
                base[(size_t)(c0 + c) * N_ + (n0 + r0 + r)] = __float2bfloat16(acc[r][c]);
        if (tx == 0) {
            float* ea = g_ev + (size_t)bh * N_ + n0;
            #pragma unroll
            for (int r = 0; r < 4; ++r)
                ea[r0 + r] = sqrtf(1.0f + ss[r]) - 1.0f;
        }
    }
}

// ---------------------------------------------------------------------------
// Kernel 2: flash attention v2. grid (16, 32), 256 threads, 2 CTAs/SM.
// SMEM: ek 2x512 | ev 2x512 | Q 16K | K 2x16K | V 2x16K  = 83968 B
// ---------------------------------------------------------------------------
#define AOFF_EK 0
#define AOFF_EV 1024
#define AOFF_Q  2048
#define AOFF_K  18432
#define AOFF_V  51200
#define SMEM_ATTN 83968

__global__ __launch_bounds__(256, 2) void attn_kernel()
{
    extern __shared__ char smc[];
    const int tid  = threadIdx.x;
    const int wid  = tid >> 5, lane = tid & 31;
    const int bh   = blockIdx.y;
    const int n0   = blockIdx.x * 128;
    const int m0   = wid * 16;
    const int g    = lane >> 2, tig = lane & 3;
    const int r    = lane & 7, grp = lane >> 3;

    const __nv_bfloat16* Kg_base = g_Ks + (size_t)bh * N_ * 64;
    const __nv_bfloat16* Vg_base = g_Vt + (size_t)bh * 64 * N_;
    const float* ekg = g_ek + (size_t)bh * N_;
    const float* evg = g_ev + (size_t)bh * N_;

    auto stage = [&](int kt) {
        const int buf = kt & 1;
        const int kn = kt * 128;
        const uint32_t Kbs = smem_u32(smc + AOFF_K + buf * 16384);
        const uint32_t Vbs = smem_u32(smc + AOFF_V + buf * 16384);
        #pragma unroll
        for (int i0 = 0; i0 < 1024; i0 += 256) {
            int i = i0 + tid;
            int row = i >> 3, c = i & 7;
            cp_async16(Kbs + SWZ128(row * 128 + c * 16),
                       (const char*)(Kg_base + (size_t)(kn + row) * 64) + c * 16);
        }
        #pragma unroll
        for (int i0 = 0; i0 < 1024; i0 += 256) {
            int i = i0 + tid;
            int d = i >> 4, c = i & 15;
            int panel = c >> 3, local = d * 128 + (c & 7) * 16;
            cp_async16(Vbs + panel * 8192 + SWZ128(local),
                       (const char*)(Vg_base + (size_t)d * N_ + kn) + c * 16);
        }
        if (tid < 32) {
            cp_async16(smem_u32(smc + AOFF_EK + buf * 512) + tid * 16,
                       (const char*)(ekg + kn) + tid * 16);
        } else if (tid < 64) {
            int t2 = tid - 32;
            cp_async16(smem_u32(smc + AOFF_EV + buf * 512) + t2 * 16,
                       (const char*)(evg + kn) + t2 * 16);
        }
        asm volatile("cp.async.commit_group;" ::: "memory");
    };

    stage(0);

    // stage Q tile (plain loads) + load resident Q fragments
    char* Qs = smc + AOFF_Q;
    const __nv_bfloat16* Qg = g_Qs + ((size_t)bh * N_ + n0) * 64;
    for (int i = tid; i < 1024; i += 256) {
        int row = i >> 3, c = i & 7;
        uint4 v = *(const uint4*)((const char*)Qg + row * 128 + c * 16);
        *(uint4*)(Qs + SWZ128(row * 128 + c * 16)) = v;
    }
    __syncthreads();
    uint32_t qa[4][4];
    {
        const uint32_t Qsb = smem_u32(Qs);
        int qrow = m0 + r + (grp & 1) * 8;
        int cb   = (grp >> 1) * 16;
        #pragma unroll
        for (int t = 0; t < 4; ++t)
            ldsm_x4(qa[t][0], qa[t][1], qa[t][2], qa[t][3],
                    Qsb + SWZ128(qrow * 128 + t * 32 + cb));
    }

    const float q0a0 = g_q0a[(size_t)bh * N_ + n0 + m0 + g];
    const float q0a1 = g_q0a[(size_t)bh * N_ + n0 + m0 + g + 8];
    float l0 = 0.f, l1 = 0.f, pe0 = 0.f, pe1 = 0.f;
    float oacc[8][4] = {};

    for (int kt = 0; kt < 16; ++kt) {
        const int buf = kt & 1;
        asm volatile("cp.async.wait_group 0;" ::: "memory");
        __syncthreads();                       // buf ready; prev buf fully consumed
        if (kt < 15) stage(kt + 1);            // prefetch overlaps compute below

        const uint32_t Ksb = smem_u32(smc + AOFF_K + buf * 16384);
        const uint32_t Vsb = smem_u32(smc + AOFF_V + buf * 16384);
        const float* ek_s = (const float*)(smc + AOFF_EK + buf * 512);
        const float* ev_s = (const float*)(smc + AOFF_EV + buf * 512);

        #pragma unroll
        for (int half = 0; half < 2; ++half) {
            // ---- S = Q K^T over 64 keys (8 n8-tiles), K=64 ----
            float sacc[8][4] = {};
            #pragma unroll
            for (int t = 0; t < 4; ++t) {
                #pragma unroll
                for (int ntp = 0; ntp < 4; ++ntp) {
                    int rowb = half * 64 + (2 * ntp + (grp >> 1)) * 8 + r;
                    uint32_t b0, b1, b2, b3;
                    ldsm_x4(b0, b1, b2, b3,
                            Ksb + SWZ128(rowb * 128 + t * 32 + (grp & 1) * 16));
                    mma_bf16(sacc[2 * ntp],     qa[t], b0, b1);
                    mma_bf16(sacc[2 * ntp + 1], qa[t], b2, b3);
                }
            }

            // ---- softmax (no max pass) + pack P fragments ----
            uint32_t pa[4][4];
            #pragma unroll
            for (int nt = 0; nt < 8; ++nt) {
                int col = half * 64 + nt * 8 + 2 * tig;
                float ekc0 = ek_s[col], ekc1 = ek_s[col + 1];
                float evc0 = ev_s[col], evc1 = ev_s[col + 1];
                float e00 = ex2f(fmaf(-q0a0, ekc0, sacc[nt][0]));
                float e01 = ex2f(fmaf(-q0a0, ekc1, sacc[nt][1]));
                float e10 = ex2f(fmaf(-q0a1, ekc0, sacc[nt][2]));
                float e11 = ex2f(fmaf(-q0a1, ekc1, sacc[nt][3]));
                l0 += e00 + e01; l1 += e10 + e11;
                pe0 = fmaf(e00, evc0, fmaf(e01, evc1, pe0));
                pe1 = fmaf(e10, evc0, fmaf(e11, evc1, pe1));
                __nv_bfloat162 t0 = __floats2bfloat162_rn(e00, e01);
                __nv_bfloat162 t1 = __floats2bfloat162_rn(e10, e11);
                pa[nt >> 1][2 * (nt & 1)]     = *(uint32_t*)&t0;
                pa[nt >> 1][2 * (nt & 1) + 1] = *(uint32_t*)&t1;
            }

            // ---- O += P V over this half (K=64: 4 k16 steps) ----
            #pragma unroll
            for (int k8 = 0; k8 < 4; ++k8) {
                int kb = k8 * 32;
                #pragma unroll
                for (int dtp = 0; dtp < 4; ++dtp) {
                    int rowd = (2 * dtp + (grp >> 1)) * 8 + r;
                    uint32_t b0, b1, b2, b3;
                    ldsm_x4(b0, b1, b2, b3,
                            Vsb + half * 8192 + SWZ128(rowd * 128 + kb + (grp & 1) * 16));
                    mma_bf16(oacc[2 * dtp],     pa[k8], b0, b1);
                    mma_bf16(oacc[2 * dtp + 1], pa[k8], b2, b3);
                }
            }
        }
    }

    // ---- epilogue: quad-reduce row stats, Lorentz-normalize, write Mid ----
    #pragma unroll
    for (int off = 1; off < 4; off <<= 1) {
        l0  += __shfl_xor_sync(0xffffffffu, l0,  off);
        l1  += __shfl_xor_sync(0xffffffffu, l1,  off);
        pe0 += __shfl_xor_sync(0xffffffffu, pe0, off);
        pe1 += __shfl_xor_sync(0xffffffffu, pe1, off);
    }
    const float il0 = 1.0f / l0, il1 = 1.0f / l1;
    const float mu00 = 1.0f + pe0 * il0, mu01 = 1.0f + pe1 * il1;
    float mr0[16], mr1[16], ss0 = 0.f, ss1 = 0.f;
    #pragma unroll
    for (int dt = 0; dt < 8; ++dt) {
        #pragma unroll
        for (int j = 0; j < 2; ++j) {
            float v0 = oacc[dt][j]     * il0;
            float v1 = oacc[dt][2 + j] * il1;
            mr0[dt * 2 + j] = v0; ss0 = fmaf(v0, v0, ss0);
            mr1[dt * 2 + j] = v1; ss1 = fmaf(v1, v1, ss1);
        }
    }
    #pragma unroll
    for (int off = 1; off < 4; off <<= 1) {
        ss0 += __shfl_xor_sync(0xffffffffu, ss0, off);
        ss1 += __shfl_xor_sync(0xffffffffu, ss1, off);
    }
    const float id0 = rsqrtf(fmaxf(mu00 * mu00 - ss0, EPSF));
    const float id1 = rsqrtf(fmaxf(mu01 * mu01 - ss1, EPSF));

    const int b = bh >> 3, h = bh & 7;
    float* d0 = g_Mid + ((size_t)(b * N_ + n0 + m0 + g)     * H_ + h) * PAD_;
    float* d1 = g_Mid + ((size_t)(b * N_ + n0 + m0 + g + 8) * H_ + h) * PAD_;
    #pragma unroll
    for (int dt = 0; dt < 8; ++dt) {
        int col = dt * 8 + 2 * tig;
        d0[1 + col]     = mr0[dt * 2]     * id0;
        d0[1 + col + 1] = mr0[dt * 2 + 1] * id0;
        d1[1 + col]     = mr1[dt * 2]     * id1;
        d1[1 + col + 1] = mr1[dt * 2 + 1] * id1;
    }
    if (tig == 0) { d0[0] = mu00 * id0; d1[0] = mu01 * id1; }
}

// ---------------------------------------------------------------------------
// Kernel 3: mean over heads, Lorentz-normalize, re-lift. Unchanged.
// ---------------------------------------------------------------------------
__global__ __launch_bounds__(256) void merge_kernel(float* __restrict__ out)
{
    const int gw = (blockIdx.x * blockDim.x + threadIdx.x) >> 5;
    const int lane = threadIdx.x & 31;
    if (gw >= B_ * N_) return;

    const float* base = g_Mid + (size_t)gw * H_ * PAD_;
    float avg[3] = {0.0f, 0.0f, 0.0f};
    {
        int k = 0;
        for (int d = lane; d < AMB_; d += 32, ++k) {
            float sacc = 0.0f;
            #pragma unroll
            for (int hh = 0; hh < H_; ++hh) sacc += base[hh * PAD_ + d];
            avg[k] = sacc * (1.0f / H_);
        }
    }
    float part = 0.0f;
    {
        int k = 0;
        for (int d = lane; d < AMB_; d += 32, ++k)
            part += ((d == 0) ? -1.0f : 1.0f) * avg[k] * avg[k];
    }
    #pragma unroll
    for (int off = 1; off < 32; off <<= 1)
        part += __shfl_xor_sync(0xffffffffu, part, off);
    const float id = rsqrtf(fmaxf(-part, EPSF));

    float p2 = 0.0f;
    {
        int k = 0;
        for (int d = lane; d < AMB_; d += 32, ++k) {
            if (d > 0) { float v = avg[k] * id; p2 += v * v; }
        }
    }
    #pragma unroll
    for (int off = 1; off < 32; off <<= 1)
        p2 += __shfl_xor_sync(0xffffffffu, p2, off);
    const float t = sqrtf(1.0f + p2);

    float* o = out + (size_t)gw * AMB_;
    {
        int k = 0;
        for (int d = lane; d < AMB_; d += 32, ++k)
            o[d] = (d == 0) ? t : avg[k] * id;
    }
}

// ---------------------------------------------------------------------------
extern "C" void kernel_launch(void* const* d_in, const int* in_sizes, int n_in,
                              void* d_out, int out_size)
{
    const float* x     = (const float*)d_in[0];
    const float* Wq    = (const float*)d_in[1];
    const float* Wk    = (const float*)d_in[2];
    const float* Wv    = (const float*)d_in[3];
    const float* bq    = (const float*)d_in[4];
    const float* bk    = (const float*)d_in[5];
    const float* bv    = (const float*)d_in[6];
    const float* scale = (const float*)d_in[7];
    (void)in_sizes; (void)n_in; (void)out_size;

    const int smem1 = (XST_ + DIN_ * PAD_) * (int)sizeof(float);   // 68640
    const int smem2 = SMEM_ATTN;                                   // 83968

    cudaFuncSetAttribute(proj_kernel, cudaFuncAttributeMaxDynamicSharedMemorySize, smem1);
    cudaFuncSetAttribute(attn_kernel, cudaFuncAttributeMaxDynamicSharedMemorySize, smem2);

    proj_kernel<<<dim3(N_ / 64, H_, B_ * 3), 256, smem1>>>(x, Wq, Wk, Wv, bq, bk, bv, scale);
    attn_kernel<<<dim3(N_ / 128, B_ * H_), 256, smem2>>>();
    merge_kernel<<<(B_ * N_ * 32) / 256, 256>>>((float*)d_out);
}